// round 9
// baseline (speedup 1.0000x reference)
#include <cuda_runtime.h>
#include <math.h>
#include <stdint.h>

#define BB   512
#define LL   256
#define HH   512
#define AD   128
#define CD   512
#define G4H  2048      // 4*H
#define BH   (BB*HH)   // 262144

// ---------------- device scratch ----------------
__device__ alignas(16) float g_gp[3 * BB * G4H];    // 12 MB: per-pair gate partials
__device__ alignas(16) float g_vbias[G4H];
__device__ alignas(16) float g_atth[BB * AD];
__device__ alignas(16) float g_scores[BB * LL];
__device__ alignas(16) float g_weight[BB * LL];
__device__ alignas(16) float g_attres[BB * CD];

__device__ __forceinline__ float sigf(float x) { return 1.0f / (1.0f + expf(-x)); }

__device__ __forceinline__ float tanh_ap(float x) {
    float y;
    asm("tanh.approx.f32 %0, %1;" : "=f"(y) : "f"(x));
    return y;
}

// D += A*B, m16n8k8 tf32 (raw fp32 bits -> HW truncates mantissa)
__device__ __forceinline__ void mma8(float* c, const uint32_t* a, const uint32_t* b) {
    asm volatile("mma.sync.aligned.m16n8k8.row.col.f32.tf32.tf32.f32 "
        "{%0,%1,%2,%3}, {%4,%5,%6,%7}, {%8,%9}, {%0,%1,%2,%3};"
        : "+f"(c[0]), "+f"(c[1]), "+f"(c[2]), "+f"(c[3])
        : "r"(a[0]), "r"(a[1]), "r"(a[2]), "r"(a[3]), "r"(b[0]), "r"(b[1]));
}

__device__ __forceinline__ void ldsm4(uint32_t* r, uint32_t saddr) {
    asm volatile("ldmatrix.sync.aligned.m8n8.x4.shared.b16 {%0,%1,%2,%3}, [%4];"
        : "=r"(r[0]), "=r"(r[1]), "=r"(r[2]), "=r"(r[3]) : "r"(saddr));
}

__device__ __forceinline__ uint32_t smaddr(const void* p) {
    return (uint32_t)__cvta_generic_to_shared(p);
}
__device__ __forceinline__ void cp16(uint32_t dst, const void* src) {
    asm volatile("cp.async.cg.shared.global [%0], [%1], 16;" :: "r"(dst), "l"(src));
}
__device__ __forceinline__ void cp_commit() { asm volatile("cp.async.commit_group;"); }
template<int N> __device__ __forceinline__ void cp_wait() {
    asm volatile("cp.async.wait_group %0;" :: "n"(N));
}

// ---------------- layer-0 bias: one warp per n, coalesced
__global__ void k_vbias(const float* __restrict__ video,
                        const float* __restrict__ w_ih0,
                        const float* __restrict__ b_ih0,
                        const float* __restrict__ b_hh0) {
    int warp = (blockIdx.x * blockDim.x + threadIdx.x) >> 5;
    int lane = threadIdx.x & 31;
    if (warp >= G4H) return;
    const float* w = w_ih0 + (size_t)warp * 1536 + 512;
    float acc = 0.0f;
    #pragma unroll
    for (int i = 0; i < 16; i++) {
        int k = i * 32 + lane;
        acc += video[k] * w[k];
    }
    #pragma unroll
    for (int o = 16; o > 0; o >>= 1)
        acc += __shfl_xor_sync(0xffffffff, acc, o);
    if (lane == 0) g_vbias[warp] = acc + b_ih0[warp] + b_hh0[warp];
}

// ====== single-pair tf32 GEMM with LDSM: g_gp[z] = A_z @ W_z^T ======
// grid (32, 8, 3), 128 threads (4 warps 2x2, warp 32x32), 64x64 tile, BK=16, 3-stage.
__global__ __launch_bounds__(128)
void k_gemm1(const float* __restrict__ A0, int lda0, const float* __restrict__ W0, int ldw0,
             const float* __restrict__ A1, int lda1, const float* __restrict__ W1, int ldw1,
             const float* __restrict__ A2, int lda2, const float* __restrict__ W2, int ldw2,
             int a0_mode)
{
    __shared__ uint32_t As[3 * 64 * 20];
    __shared__ uint32_t Bs[3 * 64 * 20];
    int tid = threadIdx.x;
    int wid = tid >> 5, lane = tid & 31;
    int m0 = blockIdx.y * 64, n0 = blockIdx.x * 64;
    int wm = (wid >> 1) * 32, wn = (wid & 1) * 32;
    int pair = blockIdx.z;

    const float* Ap = (pair == 0) ? (a0_mode ? (const float*)g_attres : A0)
                                  : ((pair == 1) ? A1 : A2);
    const float* Wp = (pair == 0) ? W0 : ((pair == 1) ? W1 : W2);
    int lda = (pair == 0) ? lda0 : ((pair == 1) ? lda1 : lda2);
    int ldw = (pair == 0) ? ldw0 : ((pair == 1) ? ldw1 : ldw2);
    float* Cout = g_gp + (size_t)pair * (BB * G4H);

    // loaders: 64 rows x 16 floats per tile per stage; 2 thr/row, 8 floats each
    int lrow = tid >> 1;               // 0..63
    int kc   = (tid & 1) * 8;          // 0 or 8
    const float* apg = Ap + (size_t)(m0 + lrow) * lda + kc;
    const float* bpg = Wp + (size_t)(n0 + lrow) * ldw + kc;
    uint32_t sa = smaddr(As + lrow * 20 + kc);
    uint32_t sb = smaddr(Bs + lrow * 20 + kc);
    const uint32_t SBY = 64 * 20 * 4;

    // LDSM per-thread address components
    int arow = (lane & 7) + ((lane >> 3) & 1) * 8;   // row within m16 tile
    int akc  = (lane >> 4) * 4;                      // k sub (0 or 4)
    int brow = (lane & 7) + ((lane >> 4) & 1) * 8;   // row within n16 tile
    int bkc  = ((lane >> 3) & 1) * 4;
    uint32_t ao0 = ((wm + arow) * 20 + akc) * 4;
    uint32_t ao1 = ((wm + 16 + arow) * 20 + akc) * 4;
    uint32_t bo0 = ((wn + brow) * 20 + bkc) * 4;
    uint32_t bo1 = ((wn + 16 + brow) * 20 + bkc) * 4;
    uint32_t asbase = smaddr(As), bsbase = smaddr(Bs);

    float acc[2][4][4];
    #pragma unroll
    for (int i = 0; i < 2; i++)
        #pragma unroll
        for (int j = 0; j < 4; j++)
            #pragma unroll
            for (int k = 0; k < 4; k++) acc[i][j][k] = 0.0f;

    #pragma unroll
    for (int st = 0; st < 3; st++) {
        int k0 = st * 16;
        cp16(sa + st * SBY, apg + k0);
        cp16(sa + st * SBY + 16, apg + k0 + 4);
        cp16(sb + st * SBY, bpg + k0);
        cp16(sb + st * SBY + 16, bpg + k0 + 4);
        cp_commit();
    }

    int stage = 0;
    for (int s = 0; s < 32; s++) {
        cp_wait<2>();
        __syncthreads();
        uint32_t ab = asbase + stage * SBY;
        uint32_t bb = bsbase + stage * SBY;
        #pragma unroll
        for (int kk = 0; kk < 16; kk += 8) {
            uint32_t af[2][4], bq[2][4];
            ldsm4(af[0], ab + ao0 + kk * 4);
            ldsm4(af[1], ab + ao1 + kk * 4);
            ldsm4(bq[0], bb + bo0 + kk * 4);
            ldsm4(bq[1], bb + bo1 + kk * 4);
            #pragma unroll
            for (int mt = 0; mt < 2; mt++)
                #pragma unroll
                for (int nt = 0; nt < 4; nt++)
                    mma8(acc[mt][nt], af[mt], &bq[nt >> 1][(nt & 1) * 2]);
        }
        __syncthreads();
        if (s < 29) {
            int k0 = (s + 3) * 16;
            cp16(sa + stage * SBY, apg + k0);
            cp16(sa + stage * SBY + 16, apg + k0 + 4);
            cp16(sb + stage * SBY, bpg + k0);
            cp16(sb + stage * SBY + 16, bpg + k0 + 4);
        }
        cp_commit();
        stage++; if (stage == 3) stage = 0;
    }

    #pragma unroll
    for (int mt = 0; mt < 2; mt++) {
        int r = m0 + wm + mt * 16 + (lane >> 2);
        #pragma unroll
        for (int nt = 0; nt < 4; nt++) {
            int c = n0 + wn + nt * 8 + 2 * (lane & 3);
            Cout[(size_t)r * G4H + c]           = acc[mt][nt][0];
            Cout[(size_t)r * G4H + c + 1]       = acc[mt][nt][1];
            Cout[(size_t)(r + 8) * G4H + c]     = acc[mt][nt][2];
            Cout[(size_t)(r + 8) * G4H + c + 1] = acc[mt][nt][3];
        }
    }
}

// ---------------- LSTM activation: sum 3 partials + bias -> (h, c)
__global__ void k_lstm_act3(const float* __restrict__ cprev,
                            const float* __restrict__ bias0, const float* __restrict__ bias1,
                            int bias_mode,
                            float* __restrict__ hout, float* __restrict__ cout,
                            float* __restrict__ hout2) {
    int idx = blockIdx.x * blockDim.x + threadIdx.x;
    if (idx >= BH) return;
    int b = idx / HH, j = idx % HH;
    size_t base = (size_t)b * G4H;
    const size_t P = (size_t)BB * G4H;
    float gs[4];
    #pragma unroll
    for (int gslot = 0; gslot < 4; gslot++) {
        int n = gslot * HH + j;
        float v = g_gp[base + n] + g_gp[P + base + n] + g_gp[2 * P + base + n];
        v += bias_mode ? g_vbias[n] : (bias0[n] + bias1[n]);
        gs[gslot] = v;
    }
    float c = sigf(gs[1]) * cprev[idx] + sigf(gs[0]) * tanhf(gs[2]);
    float h = sigf(gs[3]) * tanhf(c);
    hout[idx] = h;
    cout[idx] = c;
    if (hout2) hout2[idx] = h;
}

// ---------------- att_h = h1 @ wh.T + bh  ([B,128])
__global__ void k_atth(const float* __restrict__ h1, const float* __restrict__ wh,
                       const float* __restrict__ bh) {
    __shared__ float hs[512];
    int b = blockIdx.x, t = threadIdx.x;   // 128 threads
    for (int i = t; i < 512; i += 128) hs[i] = h1[(size_t)b * 512 + i];
    __syncthreads();
    const float* w = wh + (size_t)t * 512;
    float acc = bh[t];
    #pragma unroll 8
    for (int k = 0; k < 512; k++) acc += hs[k] * w[k];
    g_atth[b * AD + t] = acc;
}

// ====== fused attention scores: 64x128 block, 8 warps (2m x 4n, warp 32x32), LDSM ======
__global__ __launch_bounds__(256)
void k_att_scores(const float* __restrict__ clip, const float* __restrict__ wc,
                  const float* __restrict__ bc, const float* __restrict__ wa,
                  const float* __restrict__ ba) {
    __shared__ uint32_t As[2 * 64 * 20];    // 10 KB
    __shared__ uint32_t Bs[2 * 128 * 20];   // 20 KB
    __shared__ float red[64 * 17];
    __shared__ float addsh[128], wash[128];

    int tid = threadIdx.x;
    int wid = tid >> 5, lane = tid & 31;
    int m0 = blockIdx.x * 64;           // row within [B*L]
    int bidx = blockIdx.x >> 2;         // batch (4 blocks per batch, L=256)
    int wm = (wid >> 2) * 32;           // 0 or 32
    int wn = (wid & 3) * 32;            // 0,32,64,96

    if (tid < 128) {
        addsh[tid] = bc[tid] + g_atth[bidx * AD + tid];
        wash[tid] = wa[tid];
    }

    // loaders: A 64x16 (1 cp16/thr), B 128x16 (2 cp16/thr)
    int lrowA = tid >> 2;               // 0..63
    int kcA   = (tid & 3) * 4;
    int lrowB = tid >> 1;               // 0..127
    int kcB   = (tid & 1) * 8;
    const float* apg = clip + (size_t)(m0 + lrowA) * CD + kcA;
    const float* bpg = wc + (size_t)lrowB * CD + kcB;
    uint32_t sa = smaddr(As + lrowA * 20 + kcA);
    uint32_t sb = smaddr(Bs + lrowB * 20 + kcB);
    const uint32_t SA = 64 * 20 * 4, SB = 128 * 20 * 4;

    // LDSM address components
    int arow = (lane & 7) + ((lane >> 3) & 1) * 8;
    int akc  = (lane >> 4) * 4;
    int brow = (lane & 7) + ((lane >> 4) & 1) * 8;
    int bkc  = ((lane >> 3) & 1) * 4;
    uint32_t ao0 = ((wm + arow) * 20 + akc) * 4;
    uint32_t ao1 = ((wm + 16 + arow) * 20 + akc) * 4;
    uint32_t bo0 = ((wn + brow) * 20 + bkc) * 4;
    uint32_t bo1 = ((wn + 16 + brow) * 20 + bkc) * 4;
    uint32_t asbase = smaddr(As), bsbase = smaddr(Bs);

    float acc[2][4][4];
    #pragma unroll
    for (int i = 0; i < 2; i++)
        #pragma unroll
        for (int j = 0; j < 4; j++)
            #pragma unroll
            for (int k = 0; k < 4; k++) acc[i][j][k] = 0.0f;

    #pragma unroll
    for (int st = 0; st < 2; st++) {
        int k0 = st * 16;
        cp16(sa + st * SA, apg + k0);
        cp16(sb + st * SB, bpg + k0);
        cp16(sb + st * SB + 16, bpg + k0 + 4);
        cp_commit();
    }

    int stage = 0;
    for (int s = 0; s < 32; s++) {
        cp_wait<1>();
        __syncthreads();
        uint32_t ab = asbase + stage * SA;
        uint32_t bb = bsbase + stage * SB;
        #pragma unroll
        for (int kk = 0; kk < 16; kk += 8) {
            uint32_t af[2][4], bq[2][4];
            ldsm4(af[0], ab + ao0 + kk * 4);
            ldsm4(af[1], ab + ao1 + kk * 4);
            ldsm4(bq[0], bb + bo0 + kk * 4);
            ldsm4(bq[1], bb + bo1 + kk * 4);
            #pragma unroll
            for (int mt = 0; mt < 2; mt++)
                #pragma unroll
                for (int nt = 0; nt < 4; nt++)
                    mma8(acc[mt][nt], af[mt], &bq[nt >> 1][(nt & 1) * 2]);
        }
        __syncthreads();
        if (s < 30) {
            int k0 = (s + 2) * 16;
            cp16(sa + stage * SA, apg + k0);
            cp16(sb + stage * SB, bpg + k0);
            cp16(sb + stage * SB + 16, bpg + k0 + 4);
        }
        cp_commit();
        stage ^= 1;
    }

    // epilogue: HW tanh + dot with wa
    float ps[2][2] = {{0.0f, 0.0f}, {0.0f, 0.0f}};
    #pragma unroll
    for (int mt = 0; mt < 2; mt++) {
        #pragma unroll
        for (int nt = 0; nt < 4; nt++) {
            int c = wn + nt * 8 + 2 * (lane & 3);
            float a0 = addsh[c], a1 = addsh[c + 1];
            float w0 = wash[c], w1 = wash[c + 1];
            float t0 = tanh_ap(acc[mt][nt][0] + a0);
            float t1 = tanh_ap(acc[mt][nt][1] + a1);
            float t2 = tanh_ap(acc[mt][nt][2] + a0);
            float t3 = tanh_ap(acc[mt][nt][3] + a1);
            ps[mt][0] += t0 * w0 + t1 * w1;
            ps[mt][1] += t2 * w0 + t3 * w1;
        }
    }
    int slot = (wid & 3) * 4 + (lane & 3);
    #pragma unroll
    for (int mt = 0; mt < 2; mt++) {
        int r = wm + mt * 16 + (lane >> 2);
        red[r * 17 + slot] = ps[mt][0];
        red[(r + 8) * 17 + slot] = ps[mt][1];
    }
    __syncthreads();
    if (tid < 64) {
        float s = ba[0];
        #pragma unroll
        for (int k = 0; k < 16; k++) s += red[tid * 17 + k];
        g_scores[m0 + tid] = s;
    }
}

// ---------------- masked softmax + renorm (per batch row, L=256)
__global__ void k_softmax(const int* __restrict__ mask) {
    __shared__ float sh[256];
    int b = blockIdx.x, t = threadIdx.x;
    float s = g_scores[b * LL + t];
    sh[t] = s;
    __syncthreads();
    for (int o = 128; o > 0; o >>= 1) {
        if (t < o) sh[t] = fmaxf(sh[t], sh[t + o]);
        __syncthreads();
    }
    float mx = sh[0];
    __syncthreads();
    float p = expf(s - mx);
    float pm = p * (float)mask[b * LL + t];
    sh[t] = pm;
    __syncthreads();
    for (int o = 128; o > 0; o >>= 1) {
        if (t < o) sh[t] += sh[t + o];
        __syncthreads();
    }
    float denom = sh[0];
    g_weight[b * LL + t] = pm / denom;
}

// ---------------- att_res[b,c] = sum_l weight[b,l]*clip[b,l,c], 2 L-halves
__global__ void k_attres(const float* __restrict__ clip) {
    __shared__ float w[256];
    __shared__ float part[512];
    int b = blockIdx.x, t = threadIdx.x;   // 256 threads
    w[t] = g_weight[b * LL + t];
    __syncthreads();
    int half = t >> 7, tt = t & 127;
    const float* cb = clip + (size_t)b * LL * CD + (size_t)half * 128 * CD;
    const float* wl = w + half * 128;
    float4 a = make_float4(0.0f, 0.0f, 0.0f, 0.0f);
    #pragma unroll 4
    for (int l = 0; l < 128; l++) {
        float wv = wl[l];
        float4 v = *reinterpret_cast<const float4*>(cb + (size_t)l * CD + tt * 4);
        a.x += wv * v.x; a.y += wv * v.y; a.z += wv * v.z; a.w += wv * v.w;
    }
    if (half) *reinterpret_cast<float4*>(&part[tt * 4]) = a;
    __syncthreads();
    if (!half) {
        float4 p = *reinterpret_cast<const float4*>(&part[tt * 4]);
        a.x += p.x; a.y += p.y; a.z += p.z; a.w += p.w;
        *reinterpret_cast<float4*>(&g_attres[b * CD + tt * 4]) = a;
    }
}

// ---------------- launch ----------------
extern "C" void kernel_launch(void* const* d_in, const int* in_sizes, int n_in,
                              void* d_out, int out_size) {
    const float* xt      = (const float*)d_in[0];
    const float* video   = (const float*)d_in[1];
    const float* event   = (const float*)d_in[2];
    const float* clip    = (const float*)d_in[3];
    const int*   cmask   = (const int*)d_in[4];
    const float* state_h = (const float*)d_in[5];
    const float* state_c = (const float*)d_in[6];
    const float* w_ih0   = (const float*)d_in[7];
    const float* w_hh0   = (const float*)d_in[8];
    const float* b_ih0   = (const float*)d_in[9];
    const float* b_hh0   = (const float*)d_in[10];
    const float* w_ih1   = (const float*)d_in[11];
    const float* w_hh1   = (const float*)d_in[12];
    const float* b_ih1   = (const float*)d_in[13];
    const float* b_hh1   = (const float*)d_in[14];
    const float* w_ih2   = (const float*)d_in[15];
    const float* w_hh2   = (const float*)d_in[16];
    const float* b_ih2   = (const float*)d_in[17];
    const float* b_hh2   = (const float*)d_in[18];
    const float* wc      = (const float*)d_in[19];
    const float* bc      = (const float*)d_in[20];
    const float* wh      = (const float*)d_in[21];
    const float* bh      = (const float*)d_in[22];
    const float* wa      = (const float*)d_in[23];
    const float* ba      = (const float*)d_in[24];

    float* out = (float*)d_out;
    float* h2o = out;            // h2: [B,H]
    float* nh  = out + BH;       // new_h: 3 x [B,H]
    float* nc  = out + 4 * BH;   // new_c: 3 x [B,H]

    dim3 ggrid(G4H / 64, BB / 64, 3);   // (32, 8, 3)

    k_vbias<<<(G4H * 32) / 256, 256>>>(video, w_ih0, b_ih0, b_hh0);

    // layer 0
    k_gemm1<<<ggrid, 128>>>(
        xt, 512,               w_ih0, 1536,
        state_h + 2 * BH, 512, w_ih0 + 1024, 1536,
        state_h, 512,          w_hh0, 512, /*a0_mode=*/0);
    k_lstm_act3<<<BH / 256, 256>>>(state_c, b_ih0, b_hh0, /*bias_mode=*/1, nh, nc, nullptr);

    // layer 1
    k_gemm1<<<ggrid, 128>>>(
        event, 512,            w_ih1, 1024,
        nh, 512,               w_ih1 + 512, 1024,
        state_h + BH, 512,     w_hh1, 512, 0);
    k_lstm_act3<<<BH / 256, 256>>>(state_c + BH, b_ih1, b_hh1, 0, nh + BH, nc + BH, nullptr);

    // attention
    k_atth<<<BB, 128>>>(nh + BH, wh, bh);
    k_att_scores<<<(BB * LL) / 64, 256>>>(clip, wc, bc, wa, ba);
    k_softmax<<<BB, 256>>>(cmask);
    k_attres<<<BB, 256>>>(clip);

    // layer 2
    k_gemm1<<<ggrid, 128>>>(
        nullptr, 512,          w_ih2, 1024,
        nh + BH, 512,          w_ih2 + 512, 1024,
        state_h + 2 * BH, 512, w_hh2, 512, /*a0_mode=*/1);
    k_lstm_act3<<<BH / 256, 256>>>(state_c + 2 * BH, b_ih2, b_hh2, 0, nh + 2 * BH, nc + 2 * BH, h2o);
}